// round 5
// baseline (speedup 1.0000x reference)
#include <cuda_runtime.h>
#include <cuda_bf16.h>

// Shapes (fixed by the problem)
#define B_  2048
#define S_  65
#define SW  64      // S-1 walk length
#define D_  256     // IN_DIM
#define H_  8
#define L_  256

// Scratch (device globals: allocation-free)
__device__ float g_PK[H_ * SW * L_];        // PK[h][s][l] = sum_d P[s,d] Wk[h,d,l]
__device__ float g_oK[(long)B_ * H_ * L_];  // oK[b][h][l] = sum_d origin[b,d] Wk[h,d,l]
__device__ float g_res[(long)B_ * H_ * L_]; // res[b][h*L + l]

__device__ __forceinline__ float sigm(float x) {
    return 1.0f / (1.0f + __expf(-x));
}

// ---------------------------------------------------------------------------
// Generic 64-row GEMM vs per-head 256x256 weight:
//   acc[r][tid] = sum_d A[r,d] * Bw[h,d,tid]
// mode 0: C = g_PK  (PK[h][r][l])      mode 1: C = g_oK (oK[b0+r][h][l])
// Thread = output column l; 64 register accumulators (rows).
// Per d4 step: 4 coalesced weight LDG + 64 broadcast LDS.128 + 256 FFMA.
// ---------------------------------------------------------------------------
__global__ __launch_bounds__(256, 2)
void gemm64_kernel(const float* __restrict__ A, long lda, long a_tile_stride,
                   const float* __restrict__ Bw, int mode)
{
    extern __shared__ float sA[];               // 64*256 floats = 64 KB
    const int tid = threadIdx.x;
    const int h   = blockIdx.y;

    const float* Ab = A + (long)blockIdx.x * a_tile_stride;
    for (int i = tid; i < SW * D_; i += 256) {
        int r = i >> 8, d = i & 255;
        sA[i] = Ab[(long)r * lda + d];
    }
    __syncthreads();

    float acc[SW];
#pragma unroll
    for (int r = 0; r < SW; r++) acc[r] = 0.0f;

    const float* w = Bw + (long)h * D_ * L_ + tid;
#pragma unroll 2
    for (int d4 = 0; d4 < D_ / 4; d4++) {
        float w0 = w[(d4 * 4 + 0) * L_];
        float w1 = w[(d4 * 4 + 1) * L_];
        float w2 = w[(d4 * 4 + 2) * L_];
        float w3 = w[(d4 * 4 + 3) * L_];
#pragma unroll
        for (int r = 0; r < SW; r++) {
            float4 o = *reinterpret_cast<const float4*>(&sA[r * D_ + d4 * 4]);
            acc[r] = fmaf(o.x, w0, fmaf(o.y, w1, fmaf(o.z, w2, fmaf(o.w, w3, acc[r]))));
        }
    }

    if (mode == 0) {
#pragma unroll
        for (int r = 0; r < SW; r++)
            g_PK[(long)h * SW * L_ + r * L_ + tid] = acc[r];
    } else {
        long b0 = (long)blockIdx.x * SW;
#pragma unroll
        for (int r = 0; r < SW; r++)
            g_oK[((b0 + r) * H_ + h) * L_ + tid] = acc[r];
    }
}

// ---------------------------------------------------------------------------
// Fused main kernel: one CTA per batch element b, loop over heads.
//   q GEMM -> edge=cos(k*q)*W[h,l] -> score (warp+smem reduce) -> softmax(64)
//   v GEMM -> res[l] = sum_s p[s]*sigmoid(v[s,l])   (thread-local!)
// bias[h] dropped: it shifts score uniformly over s -> cancels in softmax.
// ---------------------------------------------------------------------------
__global__ __launch_bounds__(256, 2)
void main_kernel(const float* __restrict__ x,
                 const float* __restrict__ Wq,
                 const float* __restrict__ Wv,
                 const float* __restrict__ Wsc)
{
    extern __shared__ float smem[];
    float* s_walk  = smem;                 // 64*256
    float* s_part  = s_walk + SW * D_;     // 64*8   [s][warp]
    float* s_score = s_part + SW * 8;      // 64
    float* s_prob  = s_score + SW;         // 64
    float* s_misc  = s_prob + SW;          // 1

    const int tid  = threadIdx.x;
    const int b    = blockIdx.x;
    const int lane = tid & 31;
    const int wid  = tid >> 5;

    // walk = x[b, 1:65, :], contiguous 64*256 floats
    const float* wp = x + ((long)b * S_ + 1) * D_;
    for (int i = tid; i < SW * D_; i += 256) s_walk[i] = wp[i];
    __syncthreads();

    for (int h = 0; h < H_; h++) {
        // ---- q GEMM ----
        float acc[SW];
#pragma unroll
        for (int r = 0; r < SW; r++) acc[r] = 0.0f;
        const float* w = Wq + (long)h * D_ * L_ + tid;
#pragma unroll 2
        for (int d4 = 0; d4 < D_ / 4; d4++) {
            float w0 = w[(d4 * 4 + 0) * L_];
            float w1 = w[(d4 * 4 + 1) * L_];
            float w2 = w[(d4 * 4 + 2) * L_];
            float w3 = w[(d4 * 4 + 3) * L_];
#pragma unroll
            for (int r = 0; r < SW; r++) {
                float4 o = *reinterpret_cast<const float4*>(&s_walk[r * D_ + d4 * 4]);
                acc[r] = fmaf(o.x, w0, fmaf(o.y, w1, fmaf(o.z, w2, fmaf(o.w, w3, acc[r]))));
            }
        }

        // ---- edge + score partials ----
        float ok = g_oK[((long)b * H_ + h) * L_ + tid];
        float wl = Wsc[h * L_ + tid];             // W[h, l, 0]
        const float* pk = g_PK + (long)h * SW * L_ + tid;
#pragma unroll
        for (int s = 0; s < SW; s++) {
            float q  = sigm(acc[s]);
            float kk = sigm(ok + pk[s * L_]);
            float e  = __cosf(kk * q) * wl;       // bias cancels in softmax
#pragma unroll
            for (int off = 16; off; off >>= 1)
                e += __shfl_down_sync(0xffffffffu, e, off);
            if (lane == 0) s_part[s * 8 + wid] = e;
        }
        __syncthreads();

        if (tid < SW) {
            float sc = 0.0f;
#pragma unroll
            for (int wg = 0; wg < 8; wg++) sc += s_part[tid * 8 + wg];
            s_score[tid] = sc;
        }
        __syncthreads();

        // ---- softmax over 64 (warp 0) ----
        if (tid < 32) {
            float a = s_score[tid], c = s_score[tid + 32];
            float m = fmaxf(a, c);
#pragma unroll
            for (int off = 16; off; off >>= 1)
                m = fmaxf(m, __shfl_xor_sync(0xffffffffu, m, off));
            float e0 = __expf(a - m), e1 = __expf(c - m);
            float ss = e0 + e1;
#pragma unroll
            for (int off = 16; off; off >>= 1)
                ss += __shfl_xor_sync(0xffffffffu, ss, off);
            s_prob[tid]      = e0;
            s_prob[tid + 32] = e1;
            if (tid == 0) s_misc[0] = 1.0f / ss;
        }
        __syncthreads();

        // ---- v GEMM ----
#pragma unroll
        for (int r = 0; r < SW; r++) acc[r] = 0.0f;
        const float* wv = Wv + (long)h * D_ * L_ + tid;
#pragma unroll 2
        for (int d4 = 0; d4 < D_ / 4; d4++) {
            float w0 = wv[(d4 * 4 + 0) * L_];
            float w1 = wv[(d4 * 4 + 1) * L_];
            float w2 = wv[(d4 * 4 + 2) * L_];
            float w3 = wv[(d4 * 4 + 3) * L_];
#pragma unroll
            for (int r = 0; r < SW; r++) {
                float4 o = *reinterpret_cast<const float4*>(&s_walk[r * D_ + d4 * 4]);
                acc[r] = fmaf(o.x, w0, fmaf(o.y, w1, fmaf(o.z, w2, fmaf(o.w, w3, acc[r]))));
            }
        }

        // ---- weighted sum over s (thread-local in l) ----
        float inv = s_misc[0];
        float rs = 0.0f;
#pragma unroll
        for (int s = 0; s < SW; s++) rs += s_prob[s] * sigm(acc[s]);
        g_res[(long)b * (H_ * L_) + h * L_ + tid] = rs * inv;
        __syncthreads();   // protect s_part/s_score/s_prob before next head
    }
}

// ---------------------------------------------------------------------------
// out[b, 0:256]   = sigmoid(res[b,:] @ O)        (M=2048, N=256, K=2048)
// out[b, 256:512] = origin[b,:] = x[b,0,:]
// CTA = 8 batch rows, thread = output column.
// ---------------------------------------------------------------------------
__global__ __launch_bounds__(256)
void out_kernel(const float* __restrict__ x,
                const float* __restrict__ O,
                float* __restrict__ out)
{
    __shared__ __align__(16) float sA[8 * 64];
    const int tid = threadIdx.x;
    const int b0  = blockIdx.x * 8;

    float acc[8];
#pragma unroll
    for (int r = 0; r < 8; r++) acc[r] = 0.0f;

    for (int ic = 0; ic < (H_ * L_) / 64; ic++) {
        for (int i = tid; i < 8 * 64; i += 256) {
            int r = i >> 6, c = i & 63;
            sA[i] = g_res[(long)(b0 + r) * (H_ * L_) + ic * 64 + c];
        }
        __syncthreads();
        const float* o = O + (long)ic * 64 * D_ + tid;
#pragma unroll 2
        for (int i4 = 0; i4 < 16; i4++) {
            float w0 = o[(i4 * 4 + 0) * D_];
            float w1 = o[(i4 * 4 + 1) * D_];
            float w2 = o[(i4 * 4 + 2) * D_];
            float w3 = o[(i4 * 4 + 3) * D_];
#pragma unroll
            for (int r = 0; r < 8; r++) {
                float4 a = *reinterpret_cast<const float4*>(&sA[r * 64 + i4 * 4]);
                acc[r] = fmaf(a.x, w0, fmaf(a.y, w1, fmaf(a.z, w2, fmaf(a.w, w3, acc[r]))));
            }
        }
        __syncthreads();
    }

#pragma unroll
    for (int r = 0; r < 8; r++)
        out[(long)(b0 + r) * 512 + tid] = sigm(acc[r]);
#pragma unroll
    for (int r = 0; r < 8; r++)
        out[(long)(b0 + r) * 512 + 256 + tid] = x[(long)(b0 + r) * S_ * D_ + tid];
}

// ---------------------------------------------------------------------------
extern "C" void kernel_launch(void* const* d_in, const int* in_sizes, int n_in,
                              void* d_out, int out_size)
{
    const float* x   = (const float*)d_in[0];
    const float* Wq  = (const float*)d_in[1];
    const float* Wk  = (const float*)d_in[2];
    const float* Wv  = (const float*)d_in[3];
    const float* Wsc = (const float*)d_in[4];   // W (H,L,1)
    const float* O   = (const float*)d_in[5];
    const float* P   = (const float*)d_in[6];
    // d_in[7] = bias: exactly cancels in softmax, unused.
    float* out = (float*)d_out;

    const int smem_gemm = SW * D_ * (int)sizeof(float);                       // 65536
    const int smem_main = (SW * D_ + SW * 8 + SW + SW + 4) * (int)sizeof(float); // ~68 KB

    cudaFuncSetAttribute((const void*)gemm64_kernel,
                         cudaFuncAttributeMaxDynamicSharedMemorySize, smem_gemm);
    cudaFuncSetAttribute((const void*)main_kernel,
                         cudaFuncAttributeMaxDynamicSharedMemorySize, smem_main);

    // 1) PK[h,s,l] = P @ Wk[h]           (tiny)
    gemm64_kernel<<<dim3(1, H_), 256, smem_gemm>>>(P, D_, 0, Wk, 0);
    // 2) oK[b,h,l] = origin @ Wk[h]      (2.1 GF)
    gemm64_kernel<<<dim3(B_ / SW, H_), 256, smem_gemm>>>(
        x, (long)S_ * D_, (long)SW * S_ * D_, Wk, 1);
    // 3) fused q/edge/softmax/v/res      (274 GF, dominant)
    main_kernel<<<B_, 256, smem_main>>>(x, Wq, Wv, Wsc);
    // 4) res @ O -> sigmoid, + origin concat
    out_kernel<<<B_ / 8, 256>>>(x, O, out);
}

// round 6
// speedup vs baseline: 1.0012x; 1.0012x over previous
#include <cuda_runtime.h>
#include <cuda_bf16.h>

// Shapes (fixed by the problem)
#define B_  2048
#define S_  65
#define SW  64      // S-1 walk length
#define D_  256     // IN_DIM
#define H_  8
#define L_  256

// Scratch (device globals: allocation-free)
__device__ float g_PK[H_ * SW * L_];        // PK[h][s][l] = sum_d P[s,d] Wk[h,d,l]
__device__ float g_oK[(long)B_ * H_ * L_];  // oK[b][h][l] = sum_d origin[b,d] Wk[h,d,l]
__device__ float g_res[(long)B_ * H_ * L_]; // res[b][h*L + l]

__device__ __forceinline__ float sigm(float x) {
    return 1.0f / (1.0f + __expf(-x));
}

// ---------------------------------------------------------------------------
// Generic 64-row GEMM vs per-head 256x256 weight:
//   acc[r][tid] = sum_d A[r,d] * Bw[h,d,tid]
// mode 0: C = g_PK  (PK[h][r][l])      mode 1: C = g_oK (oK[b0+r][h][l])
// Thread = output column l; 64 register accumulators (rows).
// Per d4 step: 4 coalesced weight LDG + 64 broadcast LDS.128 + 256 FFMA.
// ---------------------------------------------------------------------------
__global__ __launch_bounds__(256, 2)
void gemm64_kernel(const float* __restrict__ A, long lda, long a_tile_stride,
                   const float* __restrict__ Bw, int mode)
{
    extern __shared__ float sA[];               // 64*256 floats = 64 KB
    const int tid = threadIdx.x;
    const int h   = blockIdx.y;

    const float* Ab = A + (long)blockIdx.x * a_tile_stride;
    for (int i = tid; i < SW * D_; i += 256) {
        int r = i >> 8, d = i & 255;
        sA[i] = Ab[(long)r * lda + d];
    }
    __syncthreads();

    float acc[SW];
#pragma unroll
    for (int r = 0; r < SW; r++) acc[r] = 0.0f;

    const float* w = Bw + (long)h * D_ * L_ + tid;
#pragma unroll 2
    for (int d4 = 0; d4 < D_ / 4; d4++) {
        float w0 = w[(d4 * 4 + 0) * L_];
        float w1 = w[(d4 * 4 + 1) * L_];
        float w2 = w[(d4 * 4 + 2) * L_];
        float w3 = w[(d4 * 4 + 3) * L_];
#pragma unroll
        for (int r = 0; r < SW; r++) {
            float4 o = *reinterpret_cast<const float4*>(&sA[r * D_ + d4 * 4]);
            acc[r] = fmaf(o.x, w0, fmaf(o.y, w1, fmaf(o.z, w2, fmaf(o.w, w3, acc[r]))));
        }
    }

    if (mode == 0) {
#pragma unroll
        for (int r = 0; r < SW; r++)
            g_PK[(long)h * SW * L_ + r * L_ + tid] = acc[r];
    } else {
        long b0 = (long)blockIdx.x * SW;
#pragma unroll
        for (int r = 0; r < SW; r++)
            g_oK[((b0 + r) * H_ + h) * L_ + tid] = acc[r];
    }
}

// ---------------------------------------------------------------------------
// Fused main kernel: one CTA per batch element b, loop over heads.
//   q GEMM -> edge=cos(k*q)*W[h,l] -> score (warp+smem reduce) -> softmax(64)
//   v GEMM -> res[l] = sum_s p[s]*sigmoid(v[s,l])   (thread-local!)
// bias[h] dropped: it shifts score uniformly over s -> cancels in softmax.
// ---------------------------------------------------------------------------
__global__ __launch_bounds__(256, 2)
void main_kernel(const float* __restrict__ x,
                 const float* __restrict__ Wq,
                 const float* __restrict__ Wv,
                 const float* __restrict__ Wsc)
{
    extern __shared__ float smem[];
    float* s_walk  = smem;                 // 64*256
    float* s_part  = s_walk + SW * D_;     // 64*8   [s][warp]
    float* s_score = s_part + SW * 8;      // 64
    float* s_prob  = s_score + SW;         // 64
    float* s_misc  = s_prob + SW;          // 1

    const int tid  = threadIdx.x;
    const int b    = blockIdx.x;
    const int lane = tid & 31;
    const int wid  = tid >> 5;

    // walk = x[b, 1:65, :], contiguous 64*256 floats
    const float* wp = x + ((long)b * S_ + 1) * D_;
    for (int i = tid; i < SW * D_; i += 256) s_walk[i] = wp[i];
    __syncthreads();

    for (int h = 0; h < H_; h++) {
        // ---- q GEMM ----
        float acc[SW];
#pragma unroll
        for (int r = 0; r < SW; r++) acc[r] = 0.0f;
        const float* w = Wq + (long)h * D_ * L_ + tid;
#pragma unroll 2
        for (int d4 = 0; d4 < D_ / 4; d4++) {
            float w0 = w[(d4 * 4 + 0) * L_];
            float w1 = w[(d4 * 4 + 1) * L_];
            float w2 = w[(d4 * 4 + 2) * L_];
            float w3 = w[(d4 * 4 + 3) * L_];
#pragma unroll
            for (int r = 0; r < SW; r++) {
                float4 o = *reinterpret_cast<const float4*>(&s_walk[r * D_ + d4 * 4]);
                acc[r] = fmaf(o.x, w0, fmaf(o.y, w1, fmaf(o.z, w2, fmaf(o.w, w3, acc[r]))));
            }
        }

        // ---- edge + score partials ----
        float ok = g_oK[((long)b * H_ + h) * L_ + tid];
        float wl = Wsc[h * L_ + tid];             // W[h, l, 0]
        const float* pk = g_PK + (long)h * SW * L_ + tid;
#pragma unroll
        for (int s = 0; s < SW; s++) {
            float q  = sigm(acc[s]);
            float kk = sigm(ok + pk[s * L_]);
            float e  = __cosf(kk * q) * wl;       // bias cancels in softmax
#pragma unroll
            for (int off = 16; off; off >>= 1)
                e += __shfl_down_sync(0xffffffffu, e, off);
            if (lane == 0) s_part[s * 8 + wid] = e;
        }
        __syncthreads();

        if (tid < SW) {
            float sc = 0.0f;
#pragma unroll
            for (int wg = 0; wg < 8; wg++) sc += s_part[tid * 8 + wg];
            s_score[tid] = sc;
        }
        __syncthreads();

        // ---- softmax over 64 (warp 0) ----
        if (tid < 32) {
            float a = s_score[tid], c = s_score[tid + 32];
            float m = fmaxf(a, c);
#pragma unroll
            for (int off = 16; off; off >>= 1)
                m = fmaxf(m, __shfl_xor_sync(0xffffffffu, m, off));
            float e0 = __expf(a - m), e1 = __expf(c - m);
            float ss = e0 + e1;
#pragma unroll
            for (int off = 16; off; off >>= 1)
                ss += __shfl_xor_sync(0xffffffffu, ss, off);
            s_prob[tid]      = e0;
            s_prob[tid + 32] = e1;
            if (tid == 0) s_misc[0] = 1.0f / ss;
        }
        __syncthreads();

        // ---- v GEMM ----
#pragma unroll
        for (int r = 0; r < SW; r++) acc[r] = 0.0f;
        const float* wv = Wv + (long)h * D_ * L_ + tid;
#pragma unroll 2
        for (int d4 = 0; d4 < D_ / 4; d4++) {
            float w0 = wv[(d4 * 4 + 0) * L_];
            float w1 = wv[(d4 * 4 + 1) * L_];
            float w2 = wv[(d4 * 4 + 2) * L_];
            float w3 = wv[(d4 * 4 + 3) * L_];
#pragma unroll
            for (int r = 0; r < SW; r++) {
                float4 o = *reinterpret_cast<const float4*>(&s_walk[r * D_ + d4 * 4]);
                acc[r] = fmaf(o.x, w0, fmaf(o.y, w1, fmaf(o.z, w2, fmaf(o.w, w3, acc[r]))));
            }
        }

        // ---- weighted sum over s (thread-local in l) ----
        float inv = s_misc[0];
        float rs = 0.0f;
#pragma unroll
        for (int s = 0; s < SW; s++) rs += s_prob[s] * sigm(acc[s]);
        g_res[(long)b * (H_ * L_) + h * L_ + tid] = rs * inv;
        __syncthreads();   // protect s_part/s_score/s_prob before next head
    }
}

// ---------------------------------------------------------------------------
// out[b, 0:256]   = sigmoid(res[b,:] @ O)        (M=2048, N=256, K=2048)
// out[b, 256:512] = origin[b,:] = x[b,0,:]
// CTA = 8 batch rows, thread = output column.
// ---------------------------------------------------------------------------
__global__ __launch_bounds__(256)
void out_kernel(const float* __restrict__ x,
                const float* __restrict__ O,
                float* __restrict__ out)
{
    __shared__ __align__(16) float sA[8 * 64];
    const int tid = threadIdx.x;
    const int b0  = blockIdx.x * 8;

    float acc[8];
#pragma unroll
    for (int r = 0; r < 8; r++) acc[r] = 0.0f;

    for (int ic = 0; ic < (H_ * L_) / 64; ic++) {
        for (int i = tid; i < 8 * 64; i += 256) {
            int r = i >> 6, c = i & 63;
            sA[i] = g_res[(long)(b0 + r) * (H_ * L_) + ic * 64 + c];
        }
        __syncthreads();
        const float* o = O + (long)ic * 64 * D_ + tid;
#pragma unroll 2
        for (int i4 = 0; i4 < 16; i4++) {
            float w0 = o[(i4 * 4 + 0) * D_];
            float w1 = o[(i4 * 4 + 1) * D_];
            float w2 = o[(i4 * 4 + 2) * D_];
            float w3 = o[(i4 * 4 + 3) * D_];
#pragma unroll
            for (int r = 0; r < 8; r++) {
                float4 a = *reinterpret_cast<const float4*>(&sA[r * 64 + i4 * 4]);
                acc[r] = fmaf(a.x, w0, fmaf(a.y, w1, fmaf(a.z, w2, fmaf(a.w, w3, acc[r]))));
            }
        }
        __syncthreads();
    }

#pragma unroll
    for (int r = 0; r < 8; r++)
        out[(long)(b0 + r) * 512 + tid] = sigm(acc[r]);
#pragma unroll
    for (int r = 0; r < 8; r++)
        out[(long)(b0 + r) * 512 + 256 + tid] = x[(long)(b0 + r) * S_ * D_ + tid];
}

// ---------------------------------------------------------------------------
extern "C" void kernel_launch(void* const* d_in, const int* in_sizes, int n_in,
                              void* d_out, int out_size)
{
    const float* x   = (const float*)d_in[0];
    const float* Wq  = (const float*)d_in[1];
    const float* Wk  = (const float*)d_in[2];
    const float* Wv  = (const float*)d_in[3];
    const float* Wsc = (const float*)d_in[4];   // W (H,L,1)
    const float* O   = (const float*)d_in[5];
    const float* P   = (const float*)d_in[6];
    // d_in[7] = bias: exactly cancels in softmax, unused.
    float* out = (float*)d_out;

    const int smem_gemm = SW * D_ * (int)sizeof(float);                       // 65536
    const int smem_main = (SW * D_ + SW * 8 + SW + SW + 4) * (int)sizeof(float); // ~68 KB

    cudaFuncSetAttribute((const void*)gemm64_kernel,
                         cudaFuncAttributeMaxDynamicSharedMemorySize, smem_gemm);
    cudaFuncSetAttribute((const void*)main_kernel,
                         cudaFuncAttributeMaxDynamicSharedMemorySize, smem_main);

    // 1) PK[h,s,l] = P @ Wk[h]           (tiny)
    gemm64_kernel<<<dim3(1, H_), 256, smem_gemm>>>(P, D_, 0, Wk, 0);
    // 2) oK[b,h,l] = origin @ Wk[h]      (2.1 GF)
    gemm64_kernel<<<dim3(B_ / SW, H_), 256, smem_gemm>>>(
        x, (long)S_ * D_, (long)SW * S_ * D_, Wk, 1);
    // 3) fused q/edge/softmax/v/res      (274 GF, dominant)
    main_kernel<<<B_, 256, smem_main>>>(x, Wq, Wv, Wsc);
    // 4) res @ O -> sigmoid, + origin concat
    out_kernel<<<B_ / 8, 256>>>(x, O, out);
}

// round 7
// speedup vs baseline: 1.0013x; 1.0001x over previous
#include <cuda_runtime.h>
#include <cuda_bf16.h>

// Shapes (fixed by the problem)
#define B_  2048
#define S_  65
#define SW  64      // S-1 walk length
#define D_  256     // IN_DIM
#define H_  8
#define L_  256

// Scratch (device globals: allocation-free)
__device__ float g_PK[H_ * SW * L_];        // PK[h][s][l] = sum_d P[s,d] Wk[h,d,l]
__device__ float g_oK[(long)B_ * H_ * L_];  // oK[b][h][l] = sum_d origin[b,d] Wk[h,d,l]
__device__ float g_res[(long)B_ * H_ * L_]; // res[b][h*L + l]

__device__ __forceinline__ float sigm(float x) {
    return 1.0f / (1.0f + __expf(-x));
}

// ---------------------------------------------------------------------------
// Generic 64-row GEMM vs per-head 256x256 weight:
//   acc[r][tid] = sum_d A[r,d] * Bw[h,d,tid]
// mode 0: C = g_PK  (PK[h][r][l])      mode 1: C = g_oK (oK[b0+r][h][l])
// Thread = output column l; 64 register accumulators (rows).
// Per d4 step: 4 coalesced weight LDG + 64 broadcast LDS.128 + 256 FFMA.
// ---------------------------------------------------------------------------
__global__ __launch_bounds__(256, 2)
void gemm64_kernel(const float* __restrict__ A, long lda, long a_tile_stride,
                   const float* __restrict__ Bw, int mode)
{
    extern __shared__ float sA[];               // 64*256 floats = 64 KB
    const int tid = threadIdx.x;
    const int h   = blockIdx.y;

    const float* Ab = A + (long)blockIdx.x * a_tile_stride;
    for (int i = tid; i < SW * D_; i += 256) {
        int r = i >> 8, d = i & 255;
        sA[i] = Ab[(long)r * lda + d];
    }
    __syncthreads();

    float acc[SW];
#pragma unroll
    for (int r = 0; r < SW; r++) acc[r] = 0.0f;

    const float* w = Bw + (long)h * D_ * L_ + tid;
#pragma unroll 2
    for (int d4 = 0; d4 < D_ / 4; d4++) {
        float w0 = w[(d4 * 4 + 0) * L_];
        float w1 = w[(d4 * 4 + 1) * L_];
        float w2 = w[(d4 * 4 + 2) * L_];
        float w3 = w[(d4 * 4 + 3) * L_];
#pragma unroll
        for (int r = 0; r < SW; r++) {
            float4 o = *reinterpret_cast<const float4*>(&sA[r * D_ + d4 * 4]);
            acc[r] = fmaf(o.x, w0, fmaf(o.y, w1, fmaf(o.z, w2, fmaf(o.w, w3, acc[r]))));
        }
    }

    if (mode == 0) {
#pragma unroll
        for (int r = 0; r < SW; r++)
            g_PK[(long)h * SW * L_ + r * L_ + tid] = acc[r];
    } else {
        long b0 = (long)blockIdx.x * SW;
#pragma unroll
        for (int r = 0; r < SW; r++)
            g_oK[((b0 + r) * H_ + h) * L_ + tid] = acc[r];
    }
}

// ---------------------------------------------------------------------------
// Fused main kernel: one CTA per batch element b, loop over heads.
//   q GEMM -> edge=cos(k*q)*W[h,l] -> score (warp+smem reduce) -> softmax(64)
//   v GEMM -> res[l] = sum_s p[s]*sigmoid(v[s,l])   (thread-local!)
// bias[h] dropped: it shifts score uniformly over s -> cancels in softmax.
// ---------------------------------------------------------------------------
__global__ __launch_bounds__(256, 2)
void main_kernel(const float* __restrict__ x,
                 const float* __restrict__ Wq,
                 const float* __restrict__ Wv,
                 const float* __restrict__ Wsc)
{
    extern __shared__ float smem[];
    float* s_walk  = smem;                 // 64*256
    float* s_part  = s_walk + SW * D_;     // 64*8   [s][warp]
    float* s_score = s_part + SW * 8;      // 64
    float* s_prob  = s_score + SW;         // 64
    float* s_misc  = s_prob + SW;          // 1

    const int tid  = threadIdx.x;
    const int b    = blockIdx.x;
    const int lane = tid & 31;
    const int wid  = tid >> 5;

    // walk = x[b, 1:65, :], contiguous 64*256 floats
    const float* wp = x + ((long)b * S_ + 1) * D_;
    for (int i = tid; i < SW * D_; i += 256) s_walk[i] = wp[i];
    __syncthreads();

    for (int h = 0; h < H_; h++) {
        // ---- q GEMM ----
        float acc[SW];
#pragma unroll
        for (int r = 0; r < SW; r++) acc[r] = 0.0f;
        const float* w = Wq + (long)h * D_ * L_ + tid;
#pragma unroll 2
        for (int d4 = 0; d4 < D_ / 4; d4++) {
            float w0 = w[(d4 * 4 + 0) * L_];
            float w1 = w[(d4 * 4 + 1) * L_];
            float w2 = w[(d4 * 4 + 2) * L_];
            float w3 = w[(d4 * 4 + 3) * L_];
#pragma unroll
            for (int r = 0; r < SW; r++) {
                float4 o = *reinterpret_cast<const float4*>(&s_walk[r * D_ + d4 * 4]);
                acc[r] = fmaf(o.x, w0, fmaf(o.y, w1, fmaf(o.z, w2, fmaf(o.w, w3, acc[r]))));
            }
        }

        // ---- edge + score partials ----
        float ok = g_oK[((long)b * H_ + h) * L_ + tid];
        float wl = Wsc[h * L_ + tid];             // W[h, l, 0]
        const float* pk = g_PK + (long)h * SW * L_ + tid;
#pragma unroll
        for (int s = 0; s < SW; s++) {
            float q  = sigm(acc[s]);
            float kk = sigm(ok + pk[s * L_]);
            float e  = __cosf(kk * q) * wl;       // bias cancels in softmax
#pragma unroll
            for (int off = 16; off; off >>= 1)
                e += __shfl_down_sync(0xffffffffu, e, off);
            if (lane == 0) s_part[s * 8 + wid] = e;
        }
        __syncthreads();

        if (tid < SW) {
            float sc = 0.0f;
#pragma unroll
            for (int wg = 0; wg < 8; wg++) sc += s_part[tid * 8 + wg];
            s_score[tid] = sc;
        }
        __syncthreads();

        // ---- softmax over 64 (warp 0) ----
        if (tid < 32) {
            float a = s_score[tid], c = s_score[tid + 32];
            float m = fmaxf(a, c);
#pragma unroll
            for (int off = 16; off; off >>= 1)
                m = fmaxf(m, __shfl_xor_sync(0xffffffffu, m, off));
            float e0 = __expf(a - m), e1 = __expf(c - m);
            float ss = e0 + e1;
#pragma unroll
            for (int off = 16; off; off >>= 1)
                ss += __shfl_xor_sync(0xffffffffu, ss, off);
            s_prob[tid]      = e0;
            s_prob[tid + 32] = e1;
            if (tid == 0) s_misc[0] = 1.0f / ss;
        }
        __syncthreads();

        // ---- v GEMM ----
#pragma unroll
        for (int r = 0; r < SW; r++) acc[r] = 0.0f;
        const float* wv = Wv + (long)h * D_ * L_ + tid;
#pragma unroll 2
        for (int d4 = 0; d4 < D_ / 4; d4++) {
            float w0 = wv[(d4 * 4 + 0) * L_];
            float w1 = wv[(d4 * 4 + 1) * L_];
            float w2 = wv[(d4 * 4 + 2) * L_];
            float w3 = wv[(d4 * 4 + 3) * L_];
#pragma unroll
            for (int r = 0; r < SW; r++) {
                float4 o = *reinterpret_cast<const float4*>(&s_walk[r * D_ + d4 * 4]);
                acc[r] = fmaf(o.x, w0, fmaf(o.y, w1, fmaf(o.z, w2, fmaf(o.w, w3, acc[r]))));
            }
        }

        // ---- weighted sum over s (thread-local in l) ----
        float inv = s_misc[0];
        float rs = 0.0f;
#pragma unroll
        for (int s = 0; s < SW; s++) rs += s_prob[s] * sigm(acc[s]);
        g_res[(long)b * (H_ * L_) + h * L_ + tid] = rs * inv;
        __syncthreads();   // protect s_part/s_score/s_prob before next head
    }
}

// ---------------------------------------------------------------------------
// out[b, 0:256]   = sigmoid(res[b,:] @ O)        (M=2048, N=256, K=2048)
// out[b, 256:512] = origin[b,:] = x[b,0,:]
// CTA = 8 batch rows, thread = output column.
// ---------------------------------------------------------------------------
__global__ __launch_bounds__(256)
void out_kernel(const float* __restrict__ x,
                const float* __restrict__ O,
                float* __restrict__ out)
{
    __shared__ __align__(16) float sA[8 * 64];
    const int tid = threadIdx.x;
    const int b0  = blockIdx.x * 8;

    float acc[8];
#pragma unroll
    for (int r = 0; r < 8; r++) acc[r] = 0.0f;

    for (int ic = 0; ic < (H_ * L_) / 64; ic++) {
        for (int i = tid; i < 8 * 64; i += 256) {
            int r = i >> 6, c = i & 63;
            sA[i] = g_res[(long)(b0 + r) * (H_ * L_) + ic * 64 + c];
        }
        __syncthreads();
        const float* o = O + (long)ic * 64 * D_ + tid;
#pragma unroll 2
        for (int i4 = 0; i4 < 16; i4++) {
            float w0 = o[(i4 * 4 + 0) * D_];
            float w1 = o[(i4 * 4 + 1) * D_];
            float w2 = o[(i4 * 4 + 2) * D_];
            float w3 = o[(i4 * 4 + 3) * D_];
#pragma unroll
            for (int r = 0; r < 8; r++) {
                float4 a = *reinterpret_cast<const float4*>(&sA[r * 64 + i4 * 4]);
                acc[r] = fmaf(a.x, w0, fmaf(a.y, w1, fmaf(a.z, w2, fmaf(a.w, w3, acc[r]))));
            }
        }
        __syncthreads();
    }

#pragma unroll
    for (int r = 0; r < 8; r++)
        out[(long)(b0 + r) * 512 + tid] = sigm(acc[r]);
#pragma unroll
    for (int r = 0; r < 8; r++)
        out[(long)(b0 + r) * 512 + 256 + tid] = x[(long)(b0 + r) * S_ * D_ + tid];
}

// ---------------------------------------------------------------------------
extern "C" void kernel_launch(void* const* d_in, const int* in_sizes, int n_in,
                              void* d_out, int out_size)
{
    const float* x   = (const float*)d_in[0];
    const float* Wq  = (const float*)d_in[1];
    const float* Wk  = (const float*)d_in[2];
    const float* Wv  = (const float*)d_in[3];
    const float* Wsc = (const float*)d_in[4];   // W (H,L,1)
    const float* O   = (const float*)d_in[5];
    const float* P   = (const float*)d_in[6];
    // d_in[7] = bias: exactly cancels in softmax, unused.
    float* out = (float*)d_out;

    const int smem_gemm = SW * D_ * (int)sizeof(float);                       // 65536
    const int smem_main = (SW * D_ + SW * 8 + SW + SW + 4) * (int)sizeof(float); // ~68 KB

    cudaFuncSetAttribute((const void*)gemm64_kernel,
                         cudaFuncAttributeMaxDynamicSharedMemorySize, smem_gemm);
    cudaFuncSetAttribute((const void*)main_kernel,
                         cudaFuncAttributeMaxDynamicSharedMemorySize, smem_main);

    // 1) PK[h,s,l] = P @ Wk[h]           (tiny)
    gemm64_kernel<<<dim3(1, H_), 256, smem_gemm>>>(P, D_, 0, Wk, 0);
    // 2) oK[b,h,l] = origin @ Wk[h]      (2.1 GF)
    gemm64_kernel<<<dim3(B_ / SW, H_), 256, smem_gemm>>>(
        x, (long)S_ * D_, (long)SW * S_ * D_, Wk, 1);
    // 3) fused q/edge/softmax/v/res      (274 GF, dominant)
    main_kernel<<<B_, 256, smem_main>>>(x, Wq, Wv, Wsc);
    // 4) res @ O -> sigmoid, + origin concat
    out_kernel<<<B_ / 8, 256>>>(x, O, out);
}

// round 16
// speedup vs baseline: 2.9783x; 2.9744x over previous
#include <cuda_runtime.h>
#include <cuda_bf16.h>
#include <cstdint>

// Shapes (fixed by the problem)
#define B_  2048
#define S_  65
#define SW  64      // S-1 walk length
#define D_  256     // IN_DIM
#define H_  8
#define L_  256
#define NPB 1024    // batch pairs

// ---------------------------------------------------------------------------
// Scratch (device globals: allocation-free)
// ---------------------------------------------------------------------------
__device__ float g_PK[H_ * SW * L_];        // PK[h][s][l]
__device__ float g_oK[(long)B_ * H_ * L_];  // oK[b][h][l]
__device__ float g_res[(long)B_ * H_ * L_]; // res[b][h*L + l]

// A images: [pb][term(hi=0,lo=1)][kc 0..15][khalf 0..1][r 0..127][8 bf16]
//   = ldmatrix-plane layout; 131072 B per pb.
__device__ unsigned char g_Aimg[(size_t)NPB * 131072];
// W images: [h][mat(q,v)][term][kc][khalf][l 0..255][8 bf16]; 8KB per (kc) tile.
__device__ unsigned char g_Wimg[(size_t)H_ * 2 * 2 * 16 * 8192];

__device__ __forceinline__ float sigm(float x) {
    float e = __expf(-x);
    return __fdividef(1.0f, 1.0f + e);
}

// ---------------------------------------------------------------------------
// Base-PTX tensor-core helpers (compute_103-safe: no tcgen05)
// ---------------------------------------------------------------------------
__device__ __forceinline__ uint32_t smem_u32(const void* p) {
    uint32_t a;
    asm("{ .reg .u64 t; cvta.to.shared.u64 t, %1; cvt.u32.u64 %0, t; }"
        : "=r"(a) : "l"(p));
    return a;
}
__device__ __forceinline__ void ldsm4(uint32_t& r0, uint32_t& r1,
                                      uint32_t& r2, uint32_t& r3, uint32_t addr) {
    asm volatile("ldmatrix.sync.aligned.m8n8.x4.shared.b16 {%0,%1,%2,%3}, [%4];"
                 : "=r"(r0), "=r"(r1), "=r"(r2), "=r"(r3) : "r"(addr));
}
__device__ __forceinline__ void mma16816(float* d, const uint32_t* a,
                                         uint32_t b0, uint32_t b1) {
    asm volatile("mma.sync.aligned.m16n8k16.row.col.f32.bf16.bf16.f32 "
                 "{%0,%1,%2,%3}, {%4,%5,%6,%7}, {%8,%9}, {%0,%1,%2,%3};"
                 : "+f"(d[0]), "+f"(d[1]), "+f"(d[2]), "+f"(d[3])
                 : "r"(a[0]), "r"(a[1]), "r"(a[2]), "r"(a[3]), "r"(b0), "r"(b1));
}
__device__ __forceinline__ void cpasync16(uint32_t saddr, const void* g) {
    asm volatile("cp.async.cg.shared.global [%0], [%1], 16;"
                 :: "r"(saddr), "l"(g) : "memory");
}
#define CP_COMMIT() asm volatile("cp.async.commit_group;" ::: "memory")
#define CP_WAIT0()  asm volatile("cp.async.wait_group 0;" ::: "memory")

// ---------------------------------------------------------------------------
// Prep: walk rows -> hi/lo bf16 plane images
// ---------------------------------------------------------------------------
__global__ void prepA_kernel(const float* __restrict__ x)
{
    const long total = (long)NPB * 128 * 256;
    for (long id = (long)blockIdx.x * blockDim.x + threadIdx.x; id < total;
         id += (long)gridDim.x * blockDim.x) {
        int d  = (int)(id & 255);
        int r  = (int)((id >> 8) & 127);
        int pb = (int)(id >> 15);
        int b  = pb * 2 + (r >> 6);
        int s  = r & 63;
        float v = x[((long)b * S_ + 1 + s) * D_ + d];
        __nv_bfloat16 hi = __float2bfloat16(v);
        __nv_bfloat16 lo = __float2bfloat16(v - __bfloat162float(hi));
        int kc = d >> 4, kh = (d >> 3) & 1, e = d & 7;
        size_t off = (size_t)pb * 131072 +
                     ((size_t)(kc * 2 + kh) * 128 + r) * 16 + e * 2;
        *(__nv_bfloat16*)(g_Aimg + off) = hi;
        *(__nv_bfloat16*)(g_Aimg + off + 65536) = lo;
    }
}

// Prep: Wq/Wv -> [h][mat][term][kc][khalf][l][8bf16] (B^T plane layout)
__global__ void prepW_kernel(const float* __restrict__ Wq, const float* __restrict__ Wv)
{
    const int total = H_ * 2 * 256 * 256;
    for (int id = blockIdx.x * blockDim.x + threadIdx.x; id < total;
         id += gridDim.x * blockDim.x) {
        int l   = id & 255;
        int d   = (id >> 8) & 255;
        int mat = (id >> 16) & 1;
        int h   = id >> 17;
        const float* W = mat ? Wv : Wq;
        float v = W[((long)h * D_ + d) * L_ + l];
        __nv_bfloat16 hi = __float2bfloat16(v);
        __nv_bfloat16 lo = __float2bfloat16(v - __bfloat162float(hi));
        int kc = d >> 4, kh = (d >> 3) & 1, e = d & 7;
        size_t base = ((size_t)((h * 2 + mat) * 2 + 0) * 16 + kc) * 8192 +
                      ((size_t)kh * 256 + l) * 16 + e * 2;
        *(__nv_bfloat16*)(g_Wimg + base) = hi;
        *(__nv_bfloat16*)(g_Wimg + base + 131072) = lo;  // term stride = 16*8192
    }
}

// ---------------------------------------------------------------------------
// k-path GEMMs in fp32 (small): PK and oK
// ---------------------------------------------------------------------------
__global__ __launch_bounds__(256, 2)
void gemm64_kernel(const float* __restrict__ A, long lda, long a_tile_stride,
                   const float* __restrict__ Bw, int mode)
{
    extern __shared__ float sA[];
    const int tid = threadIdx.x;
    const int h   = blockIdx.y;

    const float* Ab = A + (long)blockIdx.x * a_tile_stride;
    for (int i = tid; i < SW * D_; i += 256) {
        int r = i >> 8, d = i & 255;
        sA[i] = Ab[(long)r * lda + d];
    }
    __syncthreads();

    float acc[SW];
#pragma unroll
    for (int r = 0; r < SW; r++) acc[r] = 0.0f;

    const float* w = Bw + (long)h * D_ * L_ + tid;
#pragma unroll 2
    for (int d4 = 0; d4 < D_ / 4; d4++) {
        float w0 = w[(d4 * 4 + 0) * L_];
        float w1 = w[(d4 * 4 + 1) * L_];
        float w2 = w[(d4 * 4 + 2) * L_];
        float w3 = w[(d4 * 4 + 3) * L_];
#pragma unroll
        for (int r = 0; r < SW; r++) {
            float4 o = *reinterpret_cast<const float4*>(&sA[r * D_ + d4 * 4]);
            acc[r] = fmaf(o.x, w0, fmaf(o.y, w1, fmaf(o.z, w2, fmaf(o.w, w3, acc[r]))));
        }
    }

    if (mode == 0) {
#pragma unroll
        for (int r = 0; r < SW; r++)
            g_PK[(long)h * SW * L_ + r * L_ + tid] = acc[r];
    } else {
        long b0 = (long)blockIdx.x * SW;
#pragma unroll
        for (int r = 0; r < SW; r++)
            g_oK[((b0 + r) * H_ + h) * L_ + tid] = acc[r];
    }
}

// ---------------------------------------------------------------------------
// Main HMMA kernel. CTA = batch-pair. smem offsets:
// ---------------------------------------------------------------------------
#define SA_  0u
#define SB_  131072u        // 2 bufs x 8192
#define SPK_ 147456u        // 64 x 260 floats (padded stride)
#define SOK_ 214016u        // 2 x 256 f
#define SWL_ 216064u        // 256 f
#define SSP_ 217088u        // 256 f (score partials, [wn][row])
#define SPR_ 218112u        // 128 f (prob)
#define SVR_ 218624u        // 8 x 128 f
#define SMEM_TOTAL 222720u

__global__ __launch_bounds__(256, 1)
void mma_main_kernel(const float* __restrict__ Wsc)
{
    extern __shared__ unsigned char smem[];
    const uint32_t sb = smem_u32(smem);
    const int tid = threadIdx.x;
    const int lid = tid & 31, wid = tid >> 5;
    const int wm  = wid & 3,  wn  = wid >> 2;     // 4 x 2 warp grid (M x N)
    const int g   = lid >> 2, tig = lid & 3;
    const int pb  = blockIdx.x, b0 = pb * 2;

    float* sPK = (float*)(smem + SPK_);
    float* sOK = (float*)(smem + SOK_);
    float* sWL = (float*)(smem + SWL_);
    float* sSP = (float*)(smem + SSP_);
    float* sPR = (float*)(smem + SPR_);
    float* sVR = (float*)(smem + SVR_);

    // ---- load A images (hi+lo), resident across all heads ----
    {
        const uint4* src = (const uint4*)(g_Aimg + (size_t)pb * 131072);
        uint4* dst = (uint4*)smem;
        for (int i = tid; i < 8192; i += 256) dst[i] = src[i];
    }
    __syncthreads();

    // ldmatrix address bases (lane-dependent parts)
    const uint32_t a_lane = sb + SA_ + ((uint32_t)(lid >> 4)) * 2048u +
                            (uint32_t)(wm * 32 + (lid & 15)) * 16u;
    const uint32_t b_lane = sb + SB_ + (((uint32_t)(lid >> 3) & 1u)) * 4096u +
                            (uint32_t)(wn * 128 + ((lid >> 4) << 3) + (lid & 7)) * 16u;

    for (int h = 0; h < H_; h++) {
        for (int mat = 0; mat < 2; mat++) {
            float acc[128];
#pragma unroll
            for (int i = 0; i < 128; i++) acc[i] = 0.0f;

            const size_t hm = (size_t)(h * 2 + mat) * 262144;  // 2 terms x 131072
            __syncthreads();
            // prologue: tile 0 (term hi, kc 0) -> buf 0
            {
                const unsigned char* src = g_Wimg + hm + (size_t)tid * 16;
                uint32_t d0 = sb + SB_ + (uint32_t)tid * 16u;
                cpasync16(d0, src);
                cpasync16(d0 + 4096u, src + 4096);
                CP_COMMIT();
            }

            for (int t = 0; t < 32; t++) {
                CP_WAIT0();
                __syncthreads();
                if (t < 31) {
                    int t1 = t + 1;
                    const unsigned char* src = g_Wimg + hm +
                        (size_t)(t1 >> 4) * 131072 + (size_t)(t1 & 15) * 8192 +
                        (size_t)tid * 16;
                    uint32_t d0 = sb + SB_ + (uint32_t)((t1 & 1) * 8192) +
                                  (uint32_t)tid * 16u;
                    cpasync16(d0, src);
                    cpasync16(d0 + 4096u, src + 4096);
                    CP_COMMIT();
                }
                const int buf = t & 1, termB = t >> 4, kc = t & 15;

                // B fragments: 8 x ldmatrix.x4 covering n = wn*128 .. +127
                uint32_t bf[32];
                const uint32_t bb = b_lane + (uint32_t)(buf * 8192);
#pragma unroll
                for (int nb2 = 0; nb2 < 8; nb2++)
                    ldsm4(bf[4 * nb2 + 0], bf[4 * nb2 + 1],
                          bf[4 * nb2 + 2], bf[4 * nb2 + 3], bb + nb2 * 256u);

                // A passes: B-hi tiles take A-hi and A-lo; B-lo tiles take A-hi.
                const uint32_t ab0 = a_lane + (uint32_t)(kc * 4096);
#pragma unroll
                for (int pa = 0; pa < 2; pa++) {
                    if (pa == 1 && termB) break;
                    const uint32_t ab = ab0 + (uint32_t)(pa * 65536);
#pragma unroll
                    for (int mb = 0; mb < 2; mb++) {
                        uint32_t af[4];
                        ldsm4(af[0], af[1], af[2], af[3], ab + mb * 256u);
#pragma unroll
                        for (int nb = 0; nb < 16; nb++)
                            mma16816(acc + mb * 64 + nb * 4, af,
                                     bf[4 * (nb >> 1) + 2 * (nb & 1)],
                                     bf[4 * (nb >> 1) + 2 * (nb & 1) + 1]);
                    }
                }
            }
            __syncthreads();

            if (mat == 0) {
                // ======== score epilogue + softmax ========
                for (int i = tid; i < SW * 256; i += 256) {
                    int s = i >> 8, l = i & 255;
                    sPK[s * 260 + l] = g_PK[((long)h * SW + s) * L_ + l];
                }
                for (int i = tid; i < 512; i += 256)
                    sOK[i] = g_oK[((long)(b0 + (i >> 8)) * H_ + h) * L_ + (i & 255)];
                sWL[tid] = Wsc[h * L_ + tid];
                __syncthreads();

                const int bat = wm >> 1;
                float rp[4];
#pragma unroll
                for (int mb = 0; mb < 2; mb++) {
#pragma unroll
                    for (int ch = 0; ch < 2; ch++) {
                        int srow = (wm * 32 + mb * 16 + ch * 8 + g) & 63;
                        const float* pkr = sPK + srow * 260;
                        float r = 0.0f;
#pragma unroll
                        for (int nb = 0; nb < 16; nb++) {
#pragma unroll
                            for (int p = 0; p < 2; p++) {
                                int col = wn * 128 + nb * 8 + tig * 2 + p;
                                float qv = sigm(acc[mb * 64 + nb * 4 + ch * 2 + p]);
                                float kv = sigm(sOK[bat * 256 + col] + pkr[col]);
                                r += __cosf(kv * qv) * sWL[col];
                            }
                        }
                        rp[mb * 2 + ch] = r;
                    }
                }
#pragma unroll
                for (int m = 1; m <= 2; m <<= 1)
#pragma unroll
                    for (int i = 0; i < 4; i++)
                        rp[i] += __shfl_xor_sync(0xffffffffu, rp[i], m);
                if (tig == 0) {
#pragma unroll
                    for (int mb = 0; mb < 2; mb++)
#pragma unroll
                        for (int ch = 0; ch < 2; ch++)
                            sSP[wn * 128 + wm * 32 + mb * 16 + ch * 8 + g] =
                                rp[mb * 2 + ch];
                }
                __syncthreads();

                if (wid < 2) {   // warp 0 -> batch0, warp 1 -> batch1
                    int bb = wid;
                    float a = sSP[bb * 64 + lid]      + sSP[128 + bb * 64 + lid];
                    float c = sSP[bb * 64 + 32 + lid] + sSP[128 + bb * 64 + 32 + lid];
                    float m = fmaxf(a, c);
#pragma unroll
                    for (int off = 16; off; off >>= 1)
                        m = fmaxf(m, __shfl_xor_sync(0xffffffffu, m, off));
                    float e0 = __expf(a - m), e1 = __expf(c - m);
                    float ss = e0 + e1;
#pragma unroll
                    for (int off = 16; off; off >>= 1)
                        ss += __shfl_xor_sync(0xffffffffu, ss, off);
                    float inv = __fdividef(1.0f, ss);
                    sPR[bb * 64 + lid]      = e0 * inv;
                    sPR[bb * 64 + 32 + lid] = e1 * inv;
                }
                __syncthreads();
            } else {
                // ======== weighted-v epilogue ========
                float pr[4];
#pragma unroll
                for (int mb = 0; mb < 2; mb++)
#pragma unroll
                    for (int ch = 0; ch < 2; ch++)
                        pr[mb * 2 + ch] = sPR[wm * 32 + mb * 16 + ch * 8 + g];

                float vl[32];
#pragma unroll
                for (int nb = 0; nb < 16; nb++) {
#pragma unroll
                    for (int p = 0; p < 2; p++) {
                        float sum = 0.0f;
#pragma unroll
                        for (int mb = 0; mb < 2; mb++)
#pragma unroll
                            for (int ch = 0; ch < 2; ch++)
                                sum += pr[mb * 2 + ch] *
                                       sigm(acc[mb * 64 + nb * 4 + ch * 2 + p]);
                        vl[nb * 2 + p] = sum;
                    }
                }
#pragma unroll
                for (int m = 4; m <= 16; m <<= 1)
#pragma unroll
                    for (int i = 0; i < 32; i++)
                        vl[i] += __shfl_xor_sync(0xffffffffu, vl[i], m);
                if (g == 0) {
#pragma unroll
                    for (int i = 0; i < 32; i++) {
                        int nb = i >> 1, p = i & 1;
                        sVR[wid * 128 + nb * 8 + tig * 2 + p] = vl[i];
                    }
                }
                __syncthreads();
                for (int j = tid; j < 512; j += 256) {
                    int bb = j >> 8, l = j & 255;
                    int wnn = l >> 7, ll = l & 127;
                    float val = sVR[(wnn * 4 + bb * 2) * 128 + ll] +
                                sVR[(wnn * 4 + bb * 2 + 1) * 128 + ll];
                    g_res[((long)(b0 + bb)) * (H_ * L_) + h * L_ + l] = val;
                }
                __syncthreads();
            }
        }
    }
}

// ---------------------------------------------------------------------------
// out[b, 0:256] = sigmoid(res[b,:] @ O);  out[b, 256:512] = origin
// ---------------------------------------------------------------------------
__global__ __launch_bounds__(256)
void out_kernel(const float* __restrict__ x,
                const float* __restrict__ O,
                float* __restrict__ out)
{
    __shared__ __align__(16) float sA[8 * 64];
    const int tid = threadIdx.x;
    const int b0  = blockIdx.x * 8;

    float acc[8];
#pragma unroll
    for (int r = 0; r < 8; r++) acc[r] = 0.0f;

    for (int ic = 0; ic < (H_ * L_) / 64; ic++) {
        for (int i = tid; i < 8 * 64; i += 256) {
            int r = i >> 6, c = i & 63;
            sA[i] = g_res[(long)(b0 + r) * (H_ * L_) + ic * 64 + c];
        }
        __syncthreads();
        const float* o = O + (long)ic * 64 * D_ + tid;
#pragma unroll 2
        for (int i4 = 0; i4 < 16; i4++) {
            float w0 = o[(i4 * 4 + 0) * D_];
            float w1 = o[(i4 * 4 + 1) * D_];
            float w2 = o[(i4 * 4 + 2) * D_];
            float w3 = o[(i4 * 4 + 3) * D_];
#pragma unroll
            for (int r = 0; r < 8; r++) {
                float4 a = *reinterpret_cast<const float4*>(&sA[r * 64 + i4 * 4]);
                acc[r] = fmaf(a.x, w0, fmaf(a.y, w1, fmaf(a.z, w2, fmaf(a.w, w3, acc[r]))));
            }
        }
        __syncthreads();
    }

#pragma unroll
    for (int r = 0; r < 8; r++)
        out[(long)(b0 + r) * 512 + tid] = sigm(acc[r]);
#pragma unroll
    for (int r = 0; r < 8; r++)
        out[(long)(b0 + r) * 512 + 256 + tid] = x[(long)(b0 + r) * S_ * D_ + tid];
}

// ---------------------------------------------------------------------------
extern "C" void kernel_launch(void* const* d_in, const int* in_sizes, int n_in,
                              void* d_out, int out_size)
{
    const float* x   = (const float*)d_in[0];
    const float* Wq  = (const float*)d_in[1];
    const float* Wk  = (const float*)d_in[2];
    const float* Wv  = (const float*)d_in[3];
    const float* Wsc = (const float*)d_in[4];   // W (H,L,1)
    const float* O   = (const float*)d_in[5];
    const float* P   = (const float*)d_in[6];
    // d_in[7] = bias: exactly cancels in softmax, unused.
    float* out = (float*)d_out;

    const int smem_gemm = SW * D_ * (int)sizeof(float);

    cudaFuncSetAttribute((const void*)gemm64_kernel,
                         cudaFuncAttributeMaxDynamicSharedMemorySize, smem_gemm);
    cudaFuncSetAttribute((const void*)mma_main_kernel,
                         cudaFuncAttributeMaxDynamicSharedMemorySize, SMEM_TOTAL);

    // Prep: bf16 hi/lo split plane images for A (walk) and Wq/Wv (B^T)
    prepA_kernel<<<2048, 256>>>(x);
    prepW_kernel<<<1024, 256>>>(Wq, Wv);

    // k-path in fp32 (small)
    gemm64_kernel<<<dim3(1, H_), 256, smem_gemm>>>(P, D_, 0, Wk, 0);
    gemm64_kernel<<<dim3(B_ / SW, H_), 256, smem_gemm>>>(
        x, (long)S_ * D_, (long)SW * S_ * D_, Wk, 1);

    // main HMMA kernel: q/v tensor-core GEMMs + fused epilogue
    mma_main_kernel<<<NPB, 256, SMEM_TOTAL>>>(Wsc);

    // res @ O -> sigmoid, + origin concat
    out_kernel<<<B_ / 8, 256>>>(x, O, out);
}